// round 3
// baseline (speedup 1.0000x reference)
#include <cuda_runtime.h>
#include <cuda_bf16.h>

#define N_NODES 100000
#define N_EDGES 1600000
#define D 128
#define N_CONVS 6

// ---------------- scratch (static device memory; no allocs allowed) ----------
__device__ __align__(16) float g_bufA[N_NODES * D];
__device__ __align__(16) float g_bufB[N_NODES * D];
__device__ __align__(16) float g_mean[N_NODES * D];
__device__ float g_deg_inv[N_NODES];
__device__ int   g_deg[N_NODES];
__device__ int   g_row_ptr[N_NODES + 1];
__device__ int   g_cursor[N_NODES];
__device__ int   g_col_idx[N_EDGES];
__device__ int   g_is64;   // 1 if edge_index is int64 on device, 0 if int32

// ---------------- edge dtype detection ---------------------------------------
// Sample only LOW offsets (first 512 bytes) — in-bounds under both layouts.
__global__ void detect_kernel(const void* __restrict__ ei) {
    const long long* p64 = (const long long*)ei;
    int ok = 1;
    for (int i = 0; i < 64; i++) {
        long long v = p64[i];
        if (v < 0 || v >= N_NODES) { ok = 0; break; }
    }
    g_is64 = ok;
}

__device__ __forceinline__ int load_edge(const void* ei, long idx) {
    long long v = g_is64 ? ((const long long*)ei)[idx]
                         : (long long)((const int*)ei)[idx];
    // defensive clamp: never fault, even if detection is wrong
    if ((unsigned long long)v >= (unsigned long long)N_NODES) v = 0;
    return (int)v;
}

// ---------------- CSR build --------------------------------------------------
__global__ void zero_deg_kernel() {
    int i = blockIdx.x * blockDim.x + threadIdx.x;
    if (i < N_NODES) g_deg[i] = 0;
}

__global__ void count_deg_kernel(const void* __restrict__ ei) {
    int e = blockIdx.x * blockDim.x + threadIdx.x;
    if (e < N_EDGES) {
        int dst = load_edge(ei, (long)N_EDGES + e);
        atomicAdd(&g_deg[dst], 1);
    }
}

// single-block exclusive scan over 100k degrees; also writes cursor + deg_inv
__global__ void scan_kernel() {
    const int T = 1024;
    int tid = threadIdx.x;
    int chunk = (N_NODES + T - 1) / T;
    int start = tid * chunk;
    int end = min(start + chunk, N_NODES);

    int sum = 0;
    for (int i = start; i < end; i++) sum += g_deg[i];

    __shared__ int sh[T];
    sh[tid] = sum;
    __syncthreads();
    for (int off = 1; off < T; off <<= 1) {
        int v = (tid >= off) ? sh[tid - off] : 0;
        __syncthreads();
        sh[tid] += v;
        __syncthreads();
    }
    int run = sh[tid] - sum;   // exclusive prefix
    for (int i = start; i < end; i++) {
        int d = g_deg[i];
        g_row_ptr[i] = run;
        g_cursor[i] = run;
        g_deg_inv[i] = 1.0f / (float)max(d, 1);
        run += d;
    }
    if (tid == T - 1) g_row_ptr[N_NODES] = run;
}

__global__ void fill_csr_kernel(const void* __restrict__ ei) {
    int e = blockIdx.x * blockDim.x + threadIdx.x;
    if (e < N_EDGES) {
        int src = load_edge(ei, e);
        int dst = load_edge(ei, (long)N_EDGES + e);
        int p = atomicAdd(&g_cursor[dst], 1);
        if (p < N_EDGES) g_col_idx[p] = src;
    }
}

// ---------------- mean aggregation: one warp per node ------------------------
__global__ __launch_bounds__(256) void agg_kernel(const float* __restrict__ x) {
    int warp = (blockIdx.x * blockDim.x + threadIdx.x) >> 5;
    int lane = threadIdx.x & 31;
    if (warp >= N_NODES) return;

    int e0 = g_row_ptr[warp];
    int e1 = g_row_ptr[warp + 1];
    const float4* x4 = (const float4*)x;

    float4 acc = make_float4(0.f, 0.f, 0.f, 0.f);
    for (int e = e0; e < e1; e++) {
        int s = g_col_idx[e];
        float4 v = __ldg(&x4[(long)s * 32 + lane]);
        acc.x += v.x; acc.y += v.y; acc.z += v.z; acc.w += v.w;
    }
    float di = g_deg_inv[warp];
    acc.x *= di; acc.y *= di; acc.z *= di; acc.w *= di;
    ((float4*)g_mean)[(long)warp * 32 + lane] = acc;
}

// ---------------- fused dual SGEMM + bias + relu ------------------------------
// Y[r,:] = relu( mean[r,:]@Wl + X[r,:]@Wr + b ), block tile 128x128, K-tile 16
#define TILE_K 16
__global__ __launch_bounds__(256) void sage_gemm_kernel(
    const float* __restrict__ A0,   // mean  [N,128]
    const float* __restrict__ A1,   // x     [N,128]
    const float* __restrict__ W0,   // Wl    [128,128]
    const float* __restrict__ W1,   // Wr    [128,128]
    const float* __restrict__ bias, // [128]
    float* __restrict__ Y)
{
    __shared__ __align__(16) float As[TILE_K][128];
    __shared__ __align__(16) float Ws[TILE_K][128];

    int tid = threadIdx.x;
    int ty = tid >> 4;   // 0..15 -> row group
    int tx = tid & 15;   // 0..15 -> col group
    int row0 = blockIdx.x * 128;

    float c[8][8];
#pragma unroll
    for (int i = 0; i < 8; i++)
#pragma unroll
        for (int j = 0; j < 8; j++) c[i][j] = 0.f;

    for (int phase = 0; phase < 2; ++phase) {
        const float4* A4 = (const float4*)(phase ? A1 : A0);
        const float4* W4 = (const float4*)(phase ? W1 : W0);

        for (int k0 = 0; k0 < 128; k0 += TILE_K) {
            // A tile, stored transposed: As[k][row]
#pragma unroll
            for (int i = 0; i < 2; i++) {
                int idx = tid + i * 256;      // 0..511  (128 rows x 4 float4)
                int r = idx & 127;
                int kq = idx >> 7;            // 0..3
                int rg = row0 + r;
                if (rg >= N_NODES) rg = N_NODES - 1;   // safe dup-load, store guarded later
                float4 v = A4[(long)rg * 32 + (k0 >> 2) + kq];
                As[kq * 4 + 0][r] = v.x;
                As[kq * 4 + 1][r] = v.y;
                As[kq * 4 + 2][r] = v.z;
                As[kq * 4 + 3][r] = v.w;
            }
            // W tile: straight copy of rows k0..k0+15
#pragma unroll
            for (int i = 0; i < 2; i++) {
                int idx = tid + i * 256;      // 0..511 float4s
                ((float4*)Ws)[idx] = W4[k0 * 32 + idx];
            }
            __syncthreads();

#pragma unroll
            for (int k = 0; k < TILE_K; k++) {
                float a[8], w[8];
                *(float4*)&a[0] = *(const float4*)&As[k][ty * 8];
                *(float4*)&a[4] = *(const float4*)&As[k][ty * 8 + 4];
                *(float4*)&w[0] = *(const float4*)&Ws[k][tx * 8];
                *(float4*)&w[4] = *(const float4*)&Ws[k][tx * 8 + 4];
#pragma unroll
                for (int i = 0; i < 8; i++)
#pragma unroll
                    for (int j = 0; j < 8; j++)
                        c[i][j] = fmaf(a[i], w[j], c[i][j]);
            }
            __syncthreads();
        }
    }

    // epilogue: bias + relu
#pragma unroll
    for (int i = 0; i < 8; i++) {
        int r = row0 + ty * 8 + i;
        if (r < N_NODES) {
            float4 o0, o1;
            o0.x = fmaxf(c[i][0] + bias[tx * 8 + 0], 0.f);
            o0.y = fmaxf(c[i][1] + bias[tx * 8 + 1], 0.f);
            o0.z = fmaxf(c[i][2] + bias[tx * 8 + 2], 0.f);
            o0.w = fmaxf(c[i][3] + bias[tx * 8 + 3], 0.f);
            o1.x = fmaxf(c[i][4] + bias[tx * 8 + 4], 0.f);
            o1.y = fmaxf(c[i][5] + bias[tx * 8 + 5], 0.f);
            o1.z = fmaxf(c[i][6] + bias[tx * 8 + 6], 0.f);
            o1.w = fmaxf(c[i][7] + bias[tx * 8 + 7], 0.f);
            ((float4*)&Y[(long)r * 128])[tx * 2 + 0] = o0;
            ((float4*)&Y[(long)r * 128])[tx * 2 + 1] = o1;
        }
    }
}

// ---------------- final linear: out[n] = x[n] . W_lin + b_lin ----------------
__global__ __launch_bounds__(256) void final_kernel(
    const float* __restrict__ x, const float* __restrict__ W_lin,
    const float* __restrict__ b_lin, float* __restrict__ out)
{
    int warp = (blockIdx.x * blockDim.x + threadIdx.x) >> 5;
    int lane = threadIdx.x & 31;
    if (warp >= N_NODES) return;

    const float4* x4 = (const float4*)x;
    float4 xv = x4[(long)warp * 32 + lane];
    float w0 = W_lin[lane * 4 + 0];
    float w1 = W_lin[lane * 4 + 1];
    float w2 = W_lin[lane * 4 + 2];
    float w3 = W_lin[lane * 4 + 3];
    float s = xv.x * w0 + xv.y * w1 + xv.z * w2 + xv.w * w3;
#pragma unroll
    for (int off = 16; off > 0; off >>= 1)
        s += __shfl_xor_sync(0xFFFFFFFFu, s, off);
    if (lane == 0) out[warp] = s + b_lin[0];
}

// ---------------- launch ------------------------------------------------------
extern "C" void kernel_launch(void* const* d_in, const int* in_sizes, int n_in,
                              void* d_out, int out_size)
{
    const float* x     = (const float*)d_in[0];
    const void*  ei    = d_in[1];                 // int32 or int64, detected on device
    const float* Wl    = (const float*)d_in[2];
    const float* Wr    = (const float*)d_in[3];
    const float* b     = (const float*)d_in[4];
    const float* W_lin = (const float*)d_in[5];
    const float* b_lin = (const float*)d_in[6];
    float*       out   = (float*)d_out;

    float *bufA, *bufB, *meanp;
    cudaGetSymbolAddress((void**)&bufA, g_bufA);
    cudaGetSymbolAddress((void**)&bufB, g_bufB);
    cudaGetSymbolAddress((void**)&meanp, g_mean);

    // dtype detect + CSR build (per launch; graph-captured)
    detect_kernel<<<1, 1>>>(ei);
    zero_deg_kernel<<<(N_NODES + 255) / 256, 256>>>();
    count_deg_kernel<<<(N_EDGES + 255) / 256, 256>>>(ei);
    scan_kernel<<<1, 1024>>>();
    fill_csr_kernel<<<(N_EDGES + 255) / 256, 256>>>(ei);

    const int aggBlocks = (N_NODES * 32 + 255) / 256;
    const int gemmBlocks = (N_NODES + 127) / 128;

    const float* cur = x;
    for (int i = 0; i < N_CONVS; i++) {
        float* nxt = (i & 1) ? bufB : bufA;
        agg_kernel<<<aggBlocks, 256>>>(cur);
        sage_gemm_kernel<<<gemmBlocks, 256>>>(meanp, cur,
                                              Wl + (long)i * D * D,
                                              Wr + (long)i * D * D,
                                              b + (long)i * D,
                                              nxt);
        cur = nxt;
    }
    final_kernel<<<aggBlocks, 256>>>(cur, W_lin, b_lin, out);
}

// round 4
// speedup vs baseline: 1.2095x; 1.2095x over previous
#include <cuda_runtime.h>
#include <cuda_bf16.h>

#define N_NODES 100000
#define N_EDGES 1600000
#define D 128
#define N_CONVS 6

// ---------------- scratch (static device memory; no allocs allowed) ----------
__device__ __align__(16) float g_bufA[N_NODES * D];
__device__ __align__(16) float g_bufB[N_NODES * D];
__device__ __align__(16) float g_mean[N_NODES * D];
__device__ float g_deg_inv[N_NODES];
__device__ int   g_deg[N_NODES];
__device__ int   g_row_ptr[N_NODES + 1];
__device__ int   g_cursor[N_NODES];
__device__ int   g_col_idx[N_EDGES];
__device__ int   g_blocksum[128];
__device__ int   g_is64;   // 1 if edge_index is int64 on device, 0 if int32

// ---------------- edge dtype detection ---------------------------------------
__global__ void detect_kernel(const void* __restrict__ ei) {
    const long long* p64 = (const long long*)ei;
    int ok = 1;
    for (int i = 0; i < 64; i++) {
        long long v = p64[i];
        if (v < 0 || v >= N_NODES) { ok = 0; break; }
    }
    g_is64 = ok;
}

__device__ __forceinline__ int load_edge(const void* ei, long idx) {
    long long v = g_is64 ? ((const long long*)ei)[idx]
                         : (long long)((const int*)ei)[idx];
    if ((unsigned long long)v >= (unsigned long long)N_NODES) v = 0;
    return (int)v;
}

// ---------------- CSR build --------------------------------------------------
__global__ void zero_deg_kernel() {
    int i = blockIdx.x * blockDim.x + threadIdx.x;
    if (i < N_NODES) g_deg[i] = 0;
}

__global__ void count_deg_kernel(const void* __restrict__ ei) {
    int e = blockIdx.x * blockDim.x + threadIdx.x;
    if (e < N_EDGES) {
        int dst = load_edge(ei, (long)N_EDGES + e);
        atomicAdd(&g_deg[dst], 1);
    }
}

// ---- parallel scan: 3 small kernels ----
#define SCAN_T 1024
#define SCAN_BLOCKS ((N_NODES + SCAN_T - 1) / SCAN_T)   // 98

// per-block exclusive scan of degrees; local prefix -> g_row_ptr, block total -> g_blocksum
__global__ __launch_bounds__(SCAN_T) void scanA_kernel() {
    __shared__ int sh[SCAN_T];
    int i = blockIdx.x * SCAN_T + threadIdx.x;
    int v = (i < N_NODES) ? g_deg[i] : 0;
    sh[threadIdx.x] = v;
    __syncthreads();
    int acc = v;
    for (int off = 1; off < SCAN_T; off <<= 1) {
        int t = (threadIdx.x >= off) ? sh[threadIdx.x - off] : 0;
        __syncthreads();
        acc += t;
        sh[threadIdx.x] = acc;
        __syncthreads();
    }
    if (i < N_NODES) g_row_ptr[i] = acc - v;        // exclusive within block
    if (threadIdx.x == SCAN_T - 1) g_blocksum[blockIdx.x] = acc;
}

// exclusive scan of 98 block sums (one block)
__global__ void scanB_kernel() {
    __shared__ int sh[128];
    int t = threadIdx.x;
    int v = (t < SCAN_BLOCKS) ? g_blocksum[t] : 0;
    sh[t] = v;
    __syncthreads();
    int acc = v;
    for (int off = 1; off < 128; off <<= 1) {
        int tv = (t >= off) ? sh[t - off] : 0;
        __syncthreads();
        acc += tv;
        sh[t] = acc;
        __syncthreads();
    }
    if (t < SCAN_BLOCKS) g_blocksum[t] = acc - v;   // exclusive
}

// apply block offsets; write cursor + deg_inv; row_ptr[N] = N_EDGES
__global__ __launch_bounds__(SCAN_T) void scanC_kernel() {
    int i = blockIdx.x * SCAN_T + threadIdx.x;
    if (i < N_NODES) {
        int r = g_row_ptr[i] + g_blocksum[blockIdx.x];
        g_row_ptr[i] = r;
        g_cursor[i] = r;
        g_deg_inv[i] = 1.0f / (float)max(g_deg[i], 1);
    }
    if (i == 0) g_row_ptr[N_NODES] = N_EDGES;
}

__global__ void fill_csr_kernel(const void* __restrict__ ei) {
    int e = blockIdx.x * blockDim.x + threadIdx.x;
    if (e < N_EDGES) {
        int src = load_edge(ei, e);
        int dst = load_edge(ei, (long)N_EDGES + e);
        int p = atomicAdd(&g_cursor[dst], 1);
        if (p < N_EDGES) g_col_idx[p] = src;
    }
}

// ---------------- mean aggregation: one warp per node ------------------------
__global__ __launch_bounds__(256) void agg_kernel(const float* __restrict__ x) {
    int warp = (blockIdx.x * blockDim.x + threadIdx.x) >> 5;
    int lane = threadIdx.x & 31;
    if (warp >= N_NODES) return;

    int e0 = g_row_ptr[warp];
    int e1 = g_row_ptr[warp + 1];
    const float4* x4 = (const float4*)x;

    float4 acc = make_float4(0.f, 0.f, 0.f, 0.f);
    for (int e = e0; e < e1; e++) {
        int s = g_col_idx[e];
        float4 v = __ldg(&x4[(long)s * 32 + lane]);
        acc.x += v.x; acc.y += v.y; acc.z += v.z; acc.w += v.w;
    }
    float di = g_deg_inv[warp];
    acc.x *= di; acc.y *= di; acc.z *= di; acc.w *= di;
    ((float4*)g_mean)[(long)warp * 32 + lane] = acc;
}

// ---------------- tensor-core (3xTF32) dual GEMM + bias + relu ----------------
// Y[128-row tile, 128 cols] = relu(mean@Wl + x@Wr + b)
// block: 256 thr (8 warps); warp tile 32(M)x64(N); mma m16n8k8 tf32, fp32 accum.
#define KT 32
#define ASTRIDE 36    // floats; (4m+k)%32 distinct for fragment loads
#define WSTRIDE 132   // floats; <=2-way conflict on fragment loads

__device__ __forceinline__ unsigned f2tf32(float f) {
    unsigned r;
    asm("cvt.rna.tf32.f32 %0, %1;" : "=r"(r) : "f"(f));
    return r;
}

__device__ __forceinline__ void mma_tf32(float c[4], unsigned a0, unsigned a1,
                                         unsigned a2, unsigned a3,
                                         unsigned b0, unsigned b1) {
    asm volatile(
        "mma.sync.aligned.m16n8k8.row.col.f32.tf32.tf32.f32 "
        "{%0,%1,%2,%3}, {%4,%5,%6,%7}, {%8,%9}, {%0,%1,%2,%3};"
        : "+f"(c[0]), "+f"(c[1]), "+f"(c[2]), "+f"(c[3])
        : "r"(a0), "r"(a1), "r"(a2), "r"(a3), "r"(b0), "r"(b1));
}

__global__ __launch_bounds__(256, 1) void sage_gemm_tc_kernel(
    const float* __restrict__ A0,   // mean  [N,128]
    const float* __restrict__ A1,   // x     [N,128]
    const float* __restrict__ W0,   // Wl    [128,128] (k-major rows)
    const float* __restrict__ W1,   // Wr
    const float* __restrict__ bias, // [128]
    float* __restrict__ Y)
{
    __shared__ __align__(16) float As[128][ASTRIDE];
    __shared__ __align__(16) float Ws[KT][WSTRIDE];

    const int tid  = threadIdx.x;
    const int wid  = tid >> 5;
    const int lane = tid & 31;
    const int wm   = (wid & 3) * 32;   // warp M offset in tile
    const int wn   = (wid >> 2) * 64;  // warp N offset
    const int row0 = blockIdx.x * 128;

    float c[2][8][4];
#pragma unroll
    for (int mt = 0; mt < 2; mt++)
#pragma unroll
        for (int nt = 0; nt < 8; nt++)
#pragma unroll
            for (int i = 0; i < 4; i++) c[mt][nt][i] = 0.f;

    for (int phase = 0; phase < 2; ++phase) {
        const float4* A4 = (const float4*)(phase ? A1 : A0);
        const float4* W4 = (const float4*)(phase ? W1 : W0);

        for (int k0 = 0; k0 < 128; k0 += KT) {
            // A tile: 128 rows x 32 cols -> As[m][k]
#pragma unroll
            for (int i = 0; i < 4; i++) {
                int idx = tid + i * 256;            // 0..1023
                int r = idx >> 3;                   // 0..127
                int c4 = idx & 7;                   // 0..7
                int rg = row0 + r;
                if (rg >= N_NODES) rg = N_NODES - 1;
                float4 v = A4[(long)rg * 32 + (k0 >> 2) + c4];
                *(float4*)&As[r][c4 * 4] = v;
            }
            // W tile: 32 k-rows x 128 n -> Ws[k][n] (straight copy, coalesced)
#pragma unroll
            for (int i = 0; i < 4; i++) {
                int idx = tid + i * 256;            // 0..1023
                int k = idx >> 5;                   // 0..31
                int n4 = idx & 31;                  // 0..31
                float4 v = W4[(long)(k0 + k) * 32 + n4];
                *(float4*)&Ws[k][n4 * 4] = v;
            }
            __syncthreads();

#pragma unroll
            for (int k8 = 0; k8 < KT / 8; k8++) {
                // A fragments (2 m-tiles), split hi/lo
                unsigned ahi[2][4], alo[2][4];
#pragma unroll
                for (int mt = 0; mt < 2; mt++) {
                    int r = wm + mt * 16 + (lane >> 2);
                    int k = k8 * 8 + (lane & 3);
                    float f0 = As[r][k];
                    float f1 = As[r + 8][k];
                    float f2 = As[r][k + 4];
                    float f3 = As[r + 8][k + 4];
                    ahi[mt][0] = f2tf32(f0); alo[mt][0] = f2tf32(f0 - __uint_as_float(ahi[mt][0]));
                    ahi[mt][1] = f2tf32(f1); alo[mt][1] = f2tf32(f1 - __uint_as_float(ahi[mt][1]));
                    ahi[mt][2] = f2tf32(f2); alo[mt][2] = f2tf32(f2 - __uint_as_float(ahi[mt][2]));
                    ahi[mt][3] = f2tf32(f3); alo[mt][3] = f2tf32(f3 - __uint_as_float(ahi[mt][3]));
                }
#pragma unroll
                for (int nt = 0; nt < 8; nt++) {
                    int n = wn + nt * 8 + (lane >> 2);
                    int k = k8 * 8 + (lane & 3);
                    float g0 = Ws[k][n];
                    float g1 = Ws[k + 4][n];
                    unsigned bhi0 = f2tf32(g0), blo0 = f2tf32(g0 - __uint_as_float(bhi0));
                    unsigned bhi1 = f2tf32(g1), blo1 = f2tf32(g1 - __uint_as_float(bhi1));
#pragma unroll
                    for (int mt = 0; mt < 2; mt++) {
                        mma_tf32(c[mt][nt], ahi[mt][0], ahi[mt][1], ahi[mt][2], ahi[mt][3], bhi0, bhi1);
                        mma_tf32(c[mt][nt], ahi[mt][0], ahi[mt][1], ahi[mt][2], ahi[mt][3], blo0, blo1);
                        mma_tf32(c[mt][nt], alo[mt][0], alo[mt][1], alo[mt][2], alo[mt][3], bhi0, bhi1);
                    }
                }
            }
            __syncthreads();
        }
    }

    // epilogue: bias + relu; C frag: rows lane/4 (+8), cols 2*(lane%4)(+1)
#pragma unroll
    for (int mt = 0; mt < 2; mt++) {
#pragma unroll
        for (int half = 0; half < 2; half++) {
            int r = row0 + wm + mt * 16 + (lane >> 2) + half * 8;
            if (r < N_NODES) {
#pragma unroll
                for (int nt = 0; nt < 8; nt++) {
                    int col = wn + nt * 8 + 2 * (lane & 3);
                    float v0 = c[mt][nt][half * 2 + 0] + bias[col];
                    float v1 = c[mt][nt][half * 2 + 1] + bias[col + 1];
                    float2 o;
                    o.x = fmaxf(v0, 0.f);
                    o.y = fmaxf(v1, 0.f);
                    *(float2*)&Y[(long)r * 128 + col] = o;
                }
            }
        }
    }
}

// ---------------- final linear: out[n] = x[n] . W_lin + b_lin ----------------
__global__ __launch_bounds__(256) void final_kernel(
    const float* __restrict__ x, const float* __restrict__ W_lin,
    const float* __restrict__ b_lin, float* __restrict__ out)
{
    int warp = (blockIdx.x * blockDim.x + threadIdx.x) >> 5;
    int lane = threadIdx.x & 31;
    if (warp >= N_NODES) return;

    const float4* x4 = (const float4*)x;
    float4 xv = x4[(long)warp * 32 + lane];
    float w0 = W_lin[lane * 4 + 0];
    float w1 = W_lin[lane * 4 + 1];
    float w2 = W_lin[lane * 4 + 2];
    float w3 = W_lin[lane * 4 + 3];
    float s = xv.x * w0 + xv.y * w1 + xv.z * w2 + xv.w * w3;
#pragma unroll
    for (int off = 16; off > 0; off >>= 1)
        s += __shfl_xor_sync(0xFFFFFFFFu, s, off);
    if (lane == 0) out[warp] = s + b_lin[0];
}

// ---------------- launch ------------------------------------------------------
extern "C" void kernel_launch(void* const* d_in, const int* in_sizes, int n_in,
                              void* d_out, int out_size)
{
    const float* x     = (const float*)d_in[0];
    const void*  ei    = d_in[1];                 // int32 or int64, detected on device
    const float* Wl    = (const float*)d_in[2];
    const float* Wr    = (const float*)d_in[3];
    const float* b     = (const float*)d_in[4];
    const float* W_lin = (const float*)d_in[5];
    const float* b_lin = (const float*)d_in[6];
    float*       out   = (float*)d_out;

    float *bufA, *bufB, *meanp;
    cudaGetSymbolAddress((void**)&bufA, g_bufA);
    cudaGetSymbolAddress((void**)&bufB, g_bufB);
    cudaGetSymbolAddress((void**)&meanp, g_mean);

    // dtype detect + CSR build (per launch; graph-captured)
    detect_kernel<<<1, 1>>>(ei);
    zero_deg_kernel<<<(N_NODES + 255) / 256, 256>>>();
    count_deg_kernel<<<(N_EDGES + 255) / 256, 256>>>(ei);
    scanA_kernel<<<SCAN_BLOCKS, SCAN_T>>>();
    scanB_kernel<<<1, 128>>>();
    scanC_kernel<<<SCAN_BLOCKS, SCAN_T>>>();
    fill_csr_kernel<<<(N_EDGES + 255) / 256, 256>>>(ei);

    const int aggBlocks  = (N_NODES * 32 + 255) / 256;
    const int gemmBlocks = (N_NODES + 127) / 128;

    const float* cur = x;
    for (int i = 0; i < N_CONVS; i++) {
        float* nxt = (i & 1) ? bufB : bufA;
        agg_kernel<<<aggBlocks, 256>>>(cur);
        sage_gemm_tc_kernel<<<gemmBlocks, 256>>>(meanp, cur,
                                                 Wl + (long)i * D * D,
                                                 Wr + (long)i * D * D,
                                                 b + (long)i * D,
                                                 nxt);
        cur = nxt;
    }
    final_kernel<<<aggBlocks, 256>>>(cur, W_lin, b_lin, out);
}

// round 5
// speedup vs baseline: 1.2801x; 1.0583x over previous
#include <cuda_runtime.h>
#include <cuda_bf16.h>

#define N_NODES 100000
#define N_EDGES 1600000
#define D 128
#define N_CONVS 6

// ---------------- scratch (static device memory; no allocs allowed) ----------
__device__ __align__(16) float g_bufA[N_NODES * D];
__device__ __align__(16) float g_bufB[N_NODES * D];
__device__ __align__(16) float g_mean[N_NODES * D];
// pre-split tf32 hi/lo of all 6 layers' Wl/Wr, fragment-major:
// [layer][mat][k0t][ hi:4096 | lo:4096 ]
__device__ __align__(16) float g_Wsplit[N_CONVS * 2 * 4 * 8192];
__device__ float g_deg_inv[N_NODES];
__device__ int   g_deg[N_NODES];
__device__ int   g_row_ptr[N_NODES + 1];
__device__ int   g_cursor[N_NODES];
__device__ int   g_col_idx[N_EDGES];
__device__ int   g_blocksum[128];
__device__ int   g_is64;

// ---------------- edge dtype detection ---------------------------------------
__global__ void detect_kernel(const void* __restrict__ ei) {
    const long long* p64 = (const long long*)ei;
    int ok = 1;
    for (int i = 0; i < 64; i++) {
        long long v = p64[i];
        if (v < 0 || v >= N_NODES) { ok = 0; break; }
    }
    g_is64 = ok;
}

__device__ __forceinline__ int load_edge(const void* ei, long idx) {
    long long v = g_is64 ? ((const long long*)ei)[idx]
                         : (long long)((const int*)ei)[idx];
    if ((unsigned long long)v >= (unsigned long long)N_NODES) v = 0;
    return (int)v;
}

// ---------------- CSR build --------------------------------------------------
__global__ void zero_deg_kernel() {
    int i = blockIdx.x * blockDim.x + threadIdx.x;
    if (i < N_NODES) g_deg[i] = 0;
}

__global__ void count_deg_kernel(const void* __restrict__ ei) {
    int e = blockIdx.x * blockDim.x + threadIdx.x;
    if (e < N_EDGES) {
        int dst = load_edge(ei, (long)N_EDGES + e);
        atomicAdd(&g_deg[dst], 1);
    }
}

#define SCAN_T 1024
#define SCAN_BLOCKS ((N_NODES + SCAN_T - 1) / SCAN_T)   // 98

__global__ __launch_bounds__(SCAN_T) void scanA_kernel() {
    __shared__ int sh[SCAN_T];
    int i = blockIdx.x * SCAN_T + threadIdx.x;
    int v = (i < N_NODES) ? g_deg[i] : 0;
    sh[threadIdx.x] = v;
    __syncthreads();
    int acc = v;
    for (int off = 1; off < SCAN_T; off <<= 1) {
        int t = (threadIdx.x >= off) ? sh[threadIdx.x - off] : 0;
        __syncthreads();
        acc += t;
        sh[threadIdx.x] = acc;
        __syncthreads();
    }
    if (i < N_NODES) g_row_ptr[i] = acc - v;
    if (threadIdx.x == SCAN_T - 1) g_blocksum[blockIdx.x] = acc;
}

__global__ void scanB_kernel() {
    __shared__ int sh[128];
    int t = threadIdx.x;
    int v = (t < SCAN_BLOCKS) ? g_blocksum[t] : 0;
    sh[t] = v;
    __syncthreads();
    int acc = v;
    for (int off = 1; off < 128; off <<= 1) {
        int tv = (t >= off) ? sh[t - off] : 0;
        __syncthreads();
        acc += tv;
        sh[t] = acc;
        __syncthreads();
    }
    if (t < SCAN_BLOCKS) g_blocksum[t] = acc - v;
}

__global__ __launch_bounds__(SCAN_T) void scanC_kernel() {
    int i = blockIdx.x * SCAN_T + threadIdx.x;
    if (i < N_NODES) {
        int r = g_row_ptr[i] + g_blocksum[blockIdx.x];
        g_row_ptr[i] = r;
        g_cursor[i] = r;
        g_deg_inv[i] = 1.0f / (float)max(g_deg[i], 1);
    }
    if (i == 0) g_row_ptr[N_NODES] = N_EDGES;
}

__global__ void fill_csr_kernel(const void* __restrict__ ei) {
    int e = blockIdx.x * blockDim.x + threadIdx.x;
    if (e < N_EDGES) {
        int src = load_edge(ei, e);
        int dst = load_edge(ei, (long)N_EDGES + e);
        int p = atomicAdd(&g_cursor[dst], 1);
        if (p < N_EDGES) g_col_idx[p] = src;
    }
}

// ---------------- W pre-split (once per launch) -------------------------------
__device__ __forceinline__ float tf32_hi(float a) {
    return __uint_as_float(__float_as_uint(a) & 0xFFFFE000u);
}

__global__ void wsplit_kernel(const float* __restrict__ Wl,
                              const float* __restrict__ Wr) {
    int t = blockIdx.x * 256 + threadIdx.x;            // 6*2*4*4096 threads
    if (t >= N_CONVS * 2 * 4 * 4096) return;
    int idx   = t & 4095;
    int k0t   = (t >> 12) & 3;
    int mat   = (t >> 14) & 1;
    int layer = t >> 15;
    int h  = idx & 1;
    int q  = (idx >> 1) & 3;
    int nn = (idx >> 3) & 7;
    int nb = (idx >> 6) & 15;
    int g  = idx >> 10;
    int k = k0t * 32 + g * 8 + h * 4 + q;
    int n = nb * 8 + nn;
    const float* W = (mat ? Wr : Wl) + (long)layer * D * D;
    float w = W[k * D + n];
    float hi = tf32_hi(w);
    float lo = w - hi;
    float* dst = g_Wsplit + (long)(((layer * 2 + mat) * 4 + k0t)) * 8192;
    dst[idx] = hi;
    dst[idx + 4096] = lo;
}

// ---------------- mean aggregation: one warp per node, 4-deep ILP ------------
__global__ __launch_bounds__(256) void agg_kernel(const float* __restrict__ x) {
    int warp = (blockIdx.x * blockDim.x + threadIdx.x) >> 5;
    int lane = threadIdx.x & 31;
    if (warp >= N_NODES) return;

    int e0 = g_row_ptr[warp];
    int e1 = g_row_ptr[warp + 1];
    const float4* x4 = (const float4*)x;

    float4 a0 = make_float4(0.f, 0.f, 0.f, 0.f);
    float4 a1 = a0, a2 = a0, a3 = a0;
    int e = e0;
    for (; e + 4 <= e1; e += 4) {
        int s0 = g_col_idx[e + 0];
        int s1 = g_col_idx[e + 1];
        int s2 = g_col_idx[e + 2];
        int s3 = g_col_idx[e + 3];
        float4 v0 = __ldg(&x4[(long)s0 * 32 + lane]);
        float4 v1 = __ldg(&x4[(long)s1 * 32 + lane]);
        float4 v2 = __ldg(&x4[(long)s2 * 32 + lane]);
        float4 v3 = __ldg(&x4[(long)s3 * 32 + lane]);
        a0.x += v0.x; a0.y += v0.y; a0.z += v0.z; a0.w += v0.w;
        a1.x += v1.x; a1.y += v1.y; a1.z += v1.z; a1.w += v1.w;
        a2.x += v2.x; a2.y += v2.y; a2.z += v2.z; a2.w += v2.w;
        a3.x += v3.x; a3.y += v3.y; a3.z += v3.z; a3.w += v3.w;
    }
    for (; e < e1; e++) {
        int s = g_col_idx[e];
        float4 v = __ldg(&x4[(long)s * 32 + lane]);
        a0.x += v.x; a0.y += v.y; a0.z += v.z; a0.w += v.w;
    }
    float di = g_deg_inv[warp];
    float4 acc;
    acc.x = (a0.x + a1.x + a2.x + a3.x) * di;
    acc.y = (a0.y + a1.y + a2.y + a3.y) * di;
    acc.z = (a0.z + a1.z + a2.z + a3.z) * di;
    acc.w = (a0.w + a1.w + a2.w + a3.w) * di;
    ((float4*)g_mean)[(long)warp * 32 + lane] = acc;
}

// ---------------- tensor-core (3xTF32) dual GEMM + bias + relu ----------------
// block 256 thr (8 warps), tile 128x128, warp tile 32(M)x64(N), mma m16n8k8.
// hi/lo pre-split: A at tile load into As_hi/As_lo (stride 36);
// W pre-split in gmem fragment-major, copied linearly into smem.
#define ASTRIDE 36
#define SMEM_FLOATS (2 * 128 * ASTRIDE + 2 * 4096)   // 17408 floats = 69632 B

__device__ __forceinline__ void mma_tf32(float c[4], unsigned a0, unsigned a1,
                                         unsigned a2, unsigned a3,
                                         unsigned b0, unsigned b1) {
    asm volatile(
        "mma.sync.aligned.m16n8k8.row.col.f32.tf32.tf32.f32 "
        "{%0,%1,%2,%3}, {%4,%5,%6,%7}, {%8,%9}, {%0,%1,%2,%3};"
        : "+f"(c[0]), "+f"(c[1]), "+f"(c[2]), "+f"(c[3])
        : "r"(a0), "r"(a1), "r"(a2), "r"(a3), "r"(b0), "r"(b1));
}

__global__ __launch_bounds__(256) void sage_gemm_tc_kernel(
    const float* __restrict__ A0,    // mean  [N,128]
    const float* __restrict__ A1,    // x     [N,128]
    const float* __restrict__ Wsl,   // pre-split Wl for this layer: 4 ktiles x 8192
    const float* __restrict__ Wsr,   // pre-split Wr
    const float* __restrict__ bias,  // [128]
    float* __restrict__ Y)
{
    extern __shared__ __align__(16) float smem[];
    float* As_hi = smem;                       // 128*36
    float* As_lo = As_hi + 128 * ASTRIDE;      // 128*36
    float* Ws_hi = As_lo + 128 * ASTRIDE;      // 4096
    // Ws_lo = Ws_hi + 4096 (contiguous; filled by one linear copy)

    const int tid  = threadIdx.x;
    const int wid  = tid >> 5;
    const int lane = tid & 31;
    const int wm   = (wid & 3) * 32;
    const int wn   = (wid >> 2) * 64;
    const int row0 = blockIdx.x * 128;
    const int qq   = lane & 3;
    const int rr   = lane >> 2;

    float c[2][8][4];
#pragma unroll
    for (int mt = 0; mt < 2; mt++)
#pragma unroll
        for (int nt = 0; nt < 8; nt++)
#pragma unroll
            for (int i = 0; i < 4; i++) c[mt][nt][i] = 0.f;

    for (int phase = 0; phase < 2; ++phase) {
        const float4* A4 = (const float4*)(phase ? A1 : A0);
        const float* Wbase = phase ? Wsr : Wsl;

        for (int k0t = 0; k0t < 4; k0t++) {
            // --- A tile fill + split: 128 rows x 32 k ---
#pragma unroll
            for (int i = 0; i < 4; i++) {
                int idx = tid + i * 256;            // 0..1023 float4 slots
                int r = idx >> 3;
                int c4 = idx & 7;
                int rg = row0 + r;
                if (rg >= N_NODES) rg = N_NODES - 1;
                float4 v = A4[(long)rg * 32 + k0t * 8 + c4];
                float4 h, l;
                h.x = tf32_hi(v.x); l.x = v.x - h.x;
                h.y = tf32_hi(v.y); l.y = v.y - h.y;
                h.z = tf32_hi(v.z); l.z = v.z - h.z;
                h.w = tf32_hi(v.w); l.w = v.w - h.w;
                *(float4*)&As_hi[r * ASTRIDE + c4 * 4] = h;
                *(float4*)&As_lo[r * ASTRIDE + c4 * 4] = l;
            }
            // --- W tile fill: linear copy of 8192 floats (hi then lo) ---
            {
                const float4* src = (const float4*)(Wbase + (long)k0t * 8192);
                float4* dst = (float4*)Ws_hi;
#pragma unroll
                for (int i = 0; i < 8; i++) {
                    int idx = tid + i * 256;        // 0..2047
                    dst[idx] = src[idx];
                }
            }
            __syncthreads();

#pragma unroll
            for (int k8 = 0; k8 < 4; k8++) {
                unsigned ahi[2][4], alo[2][4];
#pragma unroll
                for (int mt = 0; mt < 2; mt++) {
                    int r = wm + mt * 16 + rr;
                    int k = k8 * 8 + qq;
                    ahi[mt][0] = __float_as_uint(As_hi[r * ASTRIDE + k]);
                    ahi[mt][1] = __float_as_uint(As_hi[(r + 8) * ASTRIDE + k]);
                    ahi[mt][2] = __float_as_uint(As_hi[r * ASTRIDE + k + 4]);
                    ahi[mt][3] = __float_as_uint(As_hi[(r + 8) * ASTRIDE + k + 4]);
                    alo[mt][0] = __float_as_uint(As_lo[r * ASTRIDE + k]);
                    alo[mt][1] = __float_as_uint(As_lo[(r + 8) * ASTRIDE + k]);
                    alo[mt][2] = __float_as_uint(As_lo[r * ASTRIDE + k + 4]);
                    alo[mt][3] = __float_as_uint(As_lo[(r + 8) * ASTRIDE + k + 4]);
                }
#pragma unroll
                for (int nt = 0; nt < 8; nt++) {
                    int bidx = ((k8 * 16 + (wn >> 3) + nt) * 8 + rr) * 8 + qq * 2;
                    float2 bh = *(const float2*)&Ws_hi[bidx];
                    float2 bl = *(const float2*)&Ws_hi[4096 + bidx];
                    unsigned bh0 = __float_as_uint(bh.x), bh1 = __float_as_uint(bh.y);
                    unsigned bl0 = __float_as_uint(bl.x), bl1 = __float_as_uint(bl.y);
#pragma unroll
                    for (int mt = 0; mt < 2; mt++) {
                        mma_tf32(c[mt][nt], ahi[mt][0], ahi[mt][1], ahi[mt][2], ahi[mt][3], bh0, bh1);
                        mma_tf32(c[mt][nt], ahi[mt][0], ahi[mt][1], ahi[mt][2], ahi[mt][3], bl0, bl1);
                        mma_tf32(c[mt][nt], alo[mt][0], alo[mt][1], alo[mt][2], alo[mt][3], bh0, bh1);
                    }
                }
            }
            __syncthreads();
        }
    }

    // epilogue: bias + relu
#pragma unroll
    for (int mt = 0; mt < 2; mt++) {
#pragma unroll
        for (int half = 0; half < 2; half++) {
            int r = row0 + wm + mt * 16 + rr + half * 8;
            if (r < N_NODES) {
#pragma unroll
                for (int nt = 0; nt < 8; nt++) {
                    int col = wn + nt * 8 + 2 * qq;
                    float v0 = c[mt][nt][half * 2 + 0] + bias[col];
                    float v1 = c[mt][nt][half * 2 + 1] + bias[col + 1];
                    float2 o;
                    o.x = fmaxf(v0, 0.f);
                    o.y = fmaxf(v1, 0.f);
                    *(float2*)&Y[(long)r * 128 + col] = o;
                }
            }
        }
    }
}

// ---------------- final linear ------------------------------------------------
__global__ __launch_bounds__(256) void final_kernel(
    const float* __restrict__ x, const float* __restrict__ W_lin,
    const float* __restrict__ b_lin, float* __restrict__ out)
{
    int warp = (blockIdx.x * blockDim.x + threadIdx.x) >> 5;
    int lane = threadIdx.x & 31;
    if (warp >= N_NODES) return;

    const float4* x4 = (const float4*)x;
    float4 xv = x4[(long)warp * 32 + lane];
    float w0 = W_lin[lane * 4 + 0];
    float w1 = W_lin[lane * 4 + 1];
    float w2 = W_lin[lane * 4 + 2];
    float w3 = W_lin[lane * 4 + 3];
    float s = xv.x * w0 + xv.y * w1 + xv.z * w2 + xv.w * w3;
#pragma unroll
    for (int off = 16; off > 0; off >>= 1)
        s += __shfl_xor_sync(0xFFFFFFFFu, s, off);
    if (lane == 0) out[warp] = s + b_lin[0];
}

// ---------------- launch ------------------------------------------------------
extern "C" void kernel_launch(void* const* d_in, const int* in_sizes, int n_in,
                              void* d_out, int out_size)
{
    const float* x     = (const float*)d_in[0];
    const void*  ei    = d_in[1];
    const float* Wl    = (const float*)d_in[2];
    const float* Wr    = (const float*)d_in[3];
    const float* b     = (const float*)d_in[4];
    const float* W_lin = (const float*)d_in[5];
    const float* b_lin = (const float*)d_in[6];
    float*       out   = (float*)d_out;

    float *bufA, *bufB, *meanp, *wsplit;
    cudaGetSymbolAddress((void**)&bufA, g_bufA);
    cudaGetSymbolAddress((void**)&bufB, g_bufB);
    cudaGetSymbolAddress((void**)&meanp, g_mean);
    cudaGetSymbolAddress((void**)&wsplit, g_Wsplit);

    const size_t smemBytes = SMEM_FLOATS * sizeof(float);   // 69632
    cudaFuncSetAttribute(sage_gemm_tc_kernel,
                         cudaFuncAttributeMaxDynamicSharedMemorySize, (int)smemBytes);

    // dtype detect + CSR build + W pre-split (per launch; graph-captured)
    detect_kernel<<<1, 1>>>(ei);
    zero_deg_kernel<<<(N_NODES + 255) / 256, 256>>>();
    count_deg_kernel<<<(N_EDGES + 255) / 256, 256>>>(ei);
    scanA_kernel<<<SCAN_BLOCKS, SCAN_T>>>();
    scanB_kernel<<<1, 128>>>();
    scanC_kernel<<<SCAN_BLOCKS, SCAN_T>>>();
    fill_csr_kernel<<<(N_EDGES + 255) / 256, 256>>>(ei);
    wsplit_kernel<<<(N_CONVS * 2 * 4 * 4096 + 255) / 256, 256>>>(Wl, Wr);

    const int aggBlocks  = (N_NODES * 32 + 255) / 256;
    const int gemmBlocks = (N_NODES + 127) / 128;

    const float* cur = x;
    for (int i = 0; i < N_CONVS; i++) {
        float* nxt = (i & 1) ? bufB : bufA;
        agg_kernel<<<aggBlocks, 256>>>(cur);
        sage_gemm_tc_kernel<<<gemmBlocks, 256, smemBytes>>>(
            meanp, cur,
            wsplit + (long)(i * 2 + 0) * 4 * 8192,
            wsplit + (long)(i * 2 + 1) * 4 * 8192,
            b + (long)i * D,
            nxt);
        cur = nxt;
    }
    final_kernel<<<aggBlocks, 256>>>(cur, W_lin, b_lin, out);
}

// round 7
// speedup vs baseline: 1.9823x; 1.5486x over previous
#include <cuda_runtime.h>
#include <cuda_bf16.h>
#include <cstdint>

#define N_NODES 100000
#define N_EDGES 1600000
#define D 128
#define N_CONVS 6

// ---------------- scratch (static device memory; no allocs allowed) ----------
__device__ __align__(16) float g_bufA[N_NODES * D];
__device__ __align__(16) float g_bufB[N_NODES * D];
__device__ __align__(16) float g_mean[N_NODES * D];
// pre-split bf16 W, fragment-major: [layer][mat][kc(4)][hi:1024 | lo:1024] uint2
__device__ __align__(16) uint2 g_Wbf[N_CONVS * 2 * 4 * 2048];
__device__ float g_deg_inv[N_NODES];
__device__ int   g_deg[N_NODES];
__device__ int   g_row_ptr[N_NODES + 1];
__device__ int   g_cursor[N_NODES];
__device__ int   g_col_idx[N_EDGES];
__device__ int   g_blocksum[128];
__device__ int   g_is64;

// ---------------- helpers -----------------------------------------------------
__device__ __forceinline__ uint32_t packbf(float a, float b) {
    __nv_bfloat162 t = __floats2bfloat162_rn(a, b);   // .x = a (low half)
    return *(uint32_t*)&t;
}
__device__ __forceinline__ float bfhi(float w) {
    return __bfloat162float(__float2bfloat16_rn(w));
}

// ---------------- edge dtype detection ---------------------------------------
__global__ void detect_kernel(const void* __restrict__ ei) {
    const long long* p64 = (const long long*)ei;
    int ok = 1;
    for (int i = 0; i < 64; i++) {
        long long v = p64[i];
        if (v < 0 || v >= N_NODES) { ok = 0; break; }
    }
    g_is64 = ok;
}

__device__ __forceinline__ int load_edge(const void* ei, long idx) {
    long long v = g_is64 ? ((const long long*)ei)[idx]
                         : (long long)((const int*)ei)[idx];
    if ((unsigned long long)v >= (unsigned long long)N_NODES) v = 0;
    return (int)v;
}

// ---------------- CSR build --------------------------------------------------
__global__ void zero_deg_kernel() {
    int i = blockIdx.x * blockDim.x + threadIdx.x;
    if (i < N_NODES) g_deg[i] = 0;
}

__global__ void count_deg_kernel(const void* __restrict__ ei) {
    int e = blockIdx.x * blockDim.x + threadIdx.x;
    if (e < N_EDGES) atomicAdd(&g_deg[load_edge(ei, (long)N_EDGES + e)], 1);
}

#define SCAN_T 1024
#define SCAN_BLOCKS ((N_NODES + SCAN_T - 1) / SCAN_T)

__global__ __launch_bounds__(SCAN_T) void scanA_kernel() {
    __shared__ int sh[SCAN_T];
    int i = blockIdx.x * SCAN_T + threadIdx.x;
    int v = (i < N_NODES) ? g_deg[i] : 0;
    sh[threadIdx.x] = v;
    __syncthreads();
    int acc = v;
    for (int off = 1; off < SCAN_T; off <<= 1) {
        int t = (threadIdx.x >= off) ? sh[threadIdx.x - off] : 0;
        __syncthreads();
        acc += t;
        sh[threadIdx.x] = acc;
        __syncthreads();
    }
    if (i < N_NODES) g_row_ptr[i] = acc - v;
    if (threadIdx.x == SCAN_T - 1) g_blocksum[blockIdx.x] = acc;
}

__global__ void scanB_kernel() {
    __shared__ int sh[128];
    int t = threadIdx.x;
    int v = (t < SCAN_BLOCKS) ? g_blocksum[t] : 0;
    sh[t] = v;
    __syncthreads();
    int acc = v;
    for (int off = 1; off < 128; off <<= 1) {
        int tv = (t >= off) ? sh[t - off] : 0;
        __syncthreads();
        acc += tv;
        sh[t] = acc;
        __syncthreads();
    }
    if (t < SCAN_BLOCKS) g_blocksum[t] = acc - v;
}

__global__ __launch_bounds__(SCAN_T) void scanC_kernel() {
    int i = blockIdx.x * SCAN_T + threadIdx.x;
    if (i < N_NODES) {
        int r = g_row_ptr[i] + g_blocksum[blockIdx.x];
        g_row_ptr[i] = r;
        g_cursor[i] = r;
        g_deg_inv[i] = 1.0f / (float)max(g_deg[i], 1);
    }
    if (i == 0) g_row_ptr[N_NODES] = N_EDGES;
}

__global__ void fill_csr_kernel(const void* __restrict__ ei) {
    int e = blockIdx.x * blockDim.x + threadIdx.x;
    if (e < N_EDGES) {
        int src = load_edge(ei, e);
        int dst = load_edge(ei, (long)N_EDGES + e);
        int p = atomicAdd(&g_cursor[dst], 1);
        if (p < N_EDGES) g_col_idx[p] = src;
    }
}

// ---------------- W pre-split to bf16 fragment-major (once per launch) --------
// Per ktile (K=32): uint2 entry f = (s*128 + n)*4 + qq  (s=k16 step, qq=lane&3)
//   .x = bf16x2 of W[kb][n], W[kb+1][n]      (kb = kc*32 + s*16 + 2qq)
//   .y = bf16x2 of W[kb+8][n], W[kb+9][n]
__global__ void wsplit_kernel(const float* __restrict__ Wl,
                              const float* __restrict__ Wr) {
    int t = blockIdx.x * 256 + threadIdx.x;           // 6*2*4*1024
    if (t >= N_CONVS * 2 * 4 * 1024) return;
    int f     = t & 1023;
    int kc    = (t >> 10) & 3;
    int mat   = (t >> 12) & 1;
    int layer = t >> 13;
    int s  = f >> 9;
    int n  = (f >> 2) & 127;
    int qq = f & 3;
    const float* W = (mat ? Wr : Wl) + (long)layer * D * D;
    int kb = kc * 32 + s * 16 + 2 * qq;
    float w0 = W[(kb + 0) * D + n];
    float w1 = W[(kb + 1) * D + n];
    float w2 = W[(kb + 8) * D + n];
    float w3 = W[(kb + 9) * D + n];
    float h0 = bfhi(w0), h1 = bfhi(w1), h2 = bfhi(w2), h3 = bfhi(w3);
    uint2 hi, lo;
    hi.x = packbf(h0, h1);        hi.y = packbf(h2, h3);
    lo.x = packbf(w0 - h0, w1 - h1);
    lo.y = packbf(w2 - h2, w3 - h3);
    uint2* dst = g_Wbf + (long)(((layer * 2 + mat) * 4 + kc)) * 2048;
    dst[f] = hi;
    dst[1024 + f] = lo;
}

// ---------------- mean aggregation: one warp per node, 4-deep ILP ------------
__global__ __launch_bounds__(256) void agg_kernel(const float* __restrict__ x) {
    int warp = (blockIdx.x * blockDim.x + threadIdx.x) >> 5;
    int lane = threadIdx.x & 31;
    if (warp >= N_NODES) return;

    int e0 = g_row_ptr[warp];
    int e1 = g_row_ptr[warp + 1];
    const float4* x4 = (const float4*)x;

    float4 a0 = make_float4(0.f, 0.f, 0.f, 0.f);
    float4 a1 = a0, a2 = a0, a3 = a0;
    int e = e0;
    for (; e + 4 <= e1; e += 4) {
        int s0 = g_col_idx[e + 0];
        int s1 = g_col_idx[e + 1];
        int s2 = g_col_idx[e + 2];
        int s3 = g_col_idx[e + 3];
        float4 v0 = __ldg(&x4[(long)s0 * 32 + lane]);
        float4 v1 = __ldg(&x4[(long)s1 * 32 + lane]);
        float4 v2 = __ldg(&x4[(long)s2 * 32 + lane]);
        float4 v3 = __ldg(&x4[(long)s3 * 32 + lane]);
        a0.x += v0.x; a0.y += v0.y; a0.z += v0.z; a0.w += v0.w;
        a1.x += v1.x; a1.y += v1.y; a1.z += v1.z; a1.w += v1.w;
        a2.x += v2.x; a2.y += v2.y; a2.z += v2.z; a2.w += v2.w;
        a3.x += v3.x; a3.y += v3.y; a3.z += v3.z; a3.w += v3.w;
    }
    for (; e < e1; e++) {
        int s = g_col_idx[e];
        float4 v = __ldg(&x4[(long)s * 32 + lane]);
        a0.x += v.x; a0.y += v.y; a0.z += v.z; a0.w += v.w;
    }
    float di = g_deg_inv[warp];
    float4 acc;
    acc.x = (a0.x + a1.x + a2.x + a3.x) * di;
    acc.y = (a0.y + a1.y + a2.y + a3.y) * di;
    acc.z = (a0.z + a1.z + a2.z + a3.z) * di;
    acc.w = (a0.w + a1.w + a2.w + a3.w) * di;
    ((float4*)g_mean)[(long)warp * 32 + lane] = acc;
}

// ---------------- 3xBF16 tensor-core dual GEMM + bias + relu ------------------
// block 256 thr (8 warps), tile 128x128, warp tile 32(M)x64(N),
// mma.sync m16n8k16 bf16 -> fp32; hi/lo split for ~fp32 accuracy.
#define APITCH 20    // uint32 per A row (16 data + 4 pad) -> bank-conflict-free

__device__ __forceinline__ void mma_bf16(float c[4],
                                         uint32_t a0, uint32_t a1,
                                         uint32_t a2, uint32_t a3,
                                         uint32_t b0, uint32_t b1) {
    asm volatile(
        "mma.sync.aligned.m16n8k16.row.col.f32.bf16.bf16.f32 "
        "{%0,%1,%2,%3}, {%4,%5,%6,%7}, {%8,%9}, {%0,%1,%2,%3};"
        : "+f"(c[0]), "+f"(c[1]), "+f"(c[2]), "+f"(c[3])
        : "r"(a0), "r"(a1), "r"(a2), "r"(a3), "r"(b0), "r"(b1));
}

__global__ __launch_bounds__(256, 2) void sage_gemm_bf16(
    const float* __restrict__ A0,    // mean [N,128]
    const float* __restrict__ A1,    // x    [N,128]
    const uint2* __restrict__ Wbf,   // this layer: [mat][kc][hi|lo] = 8*2048 uint2
    const float* __restrict__ bias,  // [128]
    float* __restrict__ Y)
{
    __shared__ __align__(16) uint32_t As[2][128][APITCH];  // [hi/lo][row][k-pair]
    __shared__ __align__(16) uint2    Ws[2][1024];         // [hi/lo][(s*128+n)*4+qq]

    const int tid  = threadIdx.x;
    const int wid  = tid >> 5;
    const int lane = tid & 31;
    const int rr   = lane >> 2;
    const int qq   = lane & 3;
    const int wm   = (wid & 3) * 32;
    const int wn   = (wid >> 2) * 64;
    const int row0 = blockIdx.x * 128;

    float c[2][8][4];
#pragma unroll
    for (int mt = 0; mt < 2; mt++)
#pragma unroll
        for (int nt = 0; nt < 8; nt++)
#pragma unroll
            for (int i = 0; i < 4; i++) c[mt][nt][i] = 0.f;

    for (int phase = 0; phase < 2; ++phase) {
        const float4* A4 = (const float4*)(phase ? A1 : A0);

        for (int kc = 0; kc < 4; kc++) {
            // --- A tile: 128 rows x 32 k, split to bf16 hi/lo, packed pairs ---
#pragma unroll
            for (int i = 0; i < 4; i++) {
                int idx = tid + i * 256;            // 0..1023 float4 slots
                int r  = idx >> 3;
                int c4 = idx & 7;
                int rg = row0 + r;
                if (rg >= N_NODES) rg = N_NODES - 1;
                float4 v = A4[(long)rg * 32 + kc * 8 + c4];
                float hx = bfhi(v.x), hy = bfhi(v.y), hz = bfhi(v.z), hw = bfhi(v.w);
                As[0][r][c4 * 2 + 0] = packbf(hx, hy);
                As[0][r][c4 * 2 + 1] = packbf(hz, hw);
                As[1][r][c4 * 2 + 0] = packbf(v.x - hx, v.y - hy);
                As[1][r][c4 * 2 + 1] = packbf(v.z - hz, v.w - hw);
            }
            // --- W tile: linear 16KB copy (hi 8KB | lo 8KB) ---
            {
                const uint4* src = (const uint4*)(Wbf + (long)(phase * 4 + kc) * 2048);
                uint4* dst = (uint4*)&Ws[0][0];
#pragma unroll
                for (int i = 0; i < 4; i++) {
                    int idx = tid + i * 256;        // 0..1023 uint4
                    dst[idx] = src[idx];
                }
            }
            __syncthreads();

#pragma unroll
            for (int s = 0; s < 2; s++) {
                uint32_t ah[2][4], al[2][4];
#pragma unroll
                for (int mt = 0; mt < 2; mt++) {
                    int r = wm + mt * 16 + rr;
                    int p = s * 8 + qq;
                    ah[mt][0] = As[0][r][p];
                    ah[mt][1] = As[0][r + 8][p];
                    ah[mt][2] = As[0][r][p + 4];
                    ah[mt][3] = As[0][r + 8][p + 4];
                    al[mt][0] = As[1][r][p];
                    al[mt][1] = As[1][r + 8][p];
                    al[mt][2] = As[1][r][p + 4];
                    al[mt][3] = As[1][r + 8][p + 4];
                }
#pragma unroll
                for (int nt = 0; nt < 8; nt++) {
                    int widx = (s * 128 + wn + nt * 8 + rr) * 4 + qq;
                    uint2 bh = Ws[0][widx];
                    uint2 bl = Ws[1][widx];
#pragma unroll
                    for (int mt = 0; mt < 2; mt++) {
                        mma_bf16(c[mt][nt], ah[mt][0], ah[mt][1], ah[mt][2], ah[mt][3], bh.x, bh.y);
                        mma_bf16(c[mt][nt], ah[mt][0], ah[mt][1], ah[mt][2], ah[mt][3], bl.x, bl.y);
                        mma_bf16(c[mt][nt], al[mt][0], al[mt][1], al[mt][2], al[mt][3], bh.x, bh.y);
                    }
                }
            }
            __syncthreads();
        }
    }

    // epilogue: bias + relu (C frag rows rr/rr+8, cols 2qq,2qq+1)
#pragma unroll
    for (int mt = 0; mt < 2; mt++) {
#pragma unroll
        for (int half = 0; half < 2; half++) {
            int r = row0 + wm + mt * 16 + rr + half * 8;
            if (r < N_NODES) {
#pragma unroll
                for (int nt = 0; nt < 8; nt++) {
                    int col = wn + nt * 8 + 2 * qq;
                    float v0 = c[mt][nt][half * 2 + 0] + bias[col];
                    float v1 = c[mt][nt][half * 2 + 1] + bias[col + 1];
                    float2 o;
                    o.x = fmaxf(v0, 0.f);
                    o.y = fmaxf(v1, 0.f);
                    *(float2*)&Y[(long)r * 128 + col] = o;
                }
            }
        }
    }
}

// ---------------- final linear ------------------------------------------------
__global__ __launch_bounds__(256) void final_kernel(
    const float* __restrict__ x, const float* __restrict__ W_lin,
    const float* __restrict__ b_lin, float* __restrict__ out)
{
    int warp = (blockIdx.x * blockDim.x + threadIdx.x) >> 5;
    int lane = threadIdx.x & 31;
    if (warp >= N_NODES) return;

    const float4* x4 = (const float4*)x;
    float4 xv = x4[(long)warp * 32 + lane];
    float w0 = W_lin[lane * 4 + 0];
    float w1 = W_lin[lane * 4 + 1];
    float w2 = W_lin[lane * 4 + 2];
    float w3 = W_lin[lane * 4 + 3];
    float s = xv.x * w0 + xv.y * w1 + xv.z * w2 + xv.w * w3;
#pragma unroll
    for (int off = 16; off > 0; off >>= 1)
        s += __shfl_xor_sync(0xFFFFFFFFu, s, off);
    if (lane == 0) out[warp] = s + b_lin[0];
}

// ---------------- launch ------------------------------------------------------
extern "C" void kernel_launch(void* const* d_in, const int* in_sizes, int n_in,
                              void* d_out, int out_size)
{
    const float* x     = (const float*)d_in[0];
    const void*  ei    = d_in[1];
    const float* Wl    = (const float*)d_in[2];
    const float* Wr    = (const float*)d_in[3];
    const float* b     = (const float*)d_in[4];
    const float* W_lin = (const float*)d_in[5];
    const float* b_lin = (const float*)d_in[6];
    float*       out   = (float*)d_out;

    float *bufA, *bufB, *meanp;
    uint2* wbf;
    cudaGetSymbolAddress((void**)&bufA, g_bufA);
    cudaGetSymbolAddress((void**)&bufB, g_bufB);
    cudaGetSymbolAddress((void**)&meanp, g_mean);
    cudaGetSymbolAddress((void**)&wbf, g_Wbf);

    detect_kernel<<<1, 1>>>(ei);
    zero_deg_kernel<<<(N_NODES + 255) / 256, 256>>>();
    count_deg_kernel<<<(N_EDGES + 255) / 256, 256>>>(ei);
    scanA_kernel<<<SCAN_BLOCKS, SCAN_T>>>();
    scanB_kernel<<<1, 128>>>();
    scanC_kernel<<<SCAN_BLOCKS, SCAN_T>>>();
    fill_csr_kernel<<<(N_EDGES + 255) / 256, 256>>>(ei);
    wsplit_kernel<<<(N_CONVS * 2 * 4 * 1024 + 255) / 256, 256>>>(Wl, Wr);

    const int aggBlocks  = (N_NODES * 32 + 255) / 256;
    const int gemmBlocks = (N_NODES + 127) / 128;

    const float* cur = x;
    for (int i = 0; i < N_CONVS; i++) {
        float* nxt = (i & 1) ? bufB : bufA;
        agg_kernel<<<aggBlocks, 256>>>(cur);
        sage_gemm_bf16<<<gemmBlocks, 256>>>(
            meanp, cur, wbf + (long)i * 8 * 2048, b + (long)i * D, nxt);
        cur = nxt;
    }
    final_kernel<<<aggBlocks, 256>>>(cur, W_lin, b_lin, out);
}